// round 2
// baseline (speedup 1.0000x reference)
#include <cuda_runtime.h>
#include <cstdint>

// ---------------------------------------------------------------------------
// Problem: B=16384, Q=1024, F=2, D=5
//  amp:  h1 = gelu(LN(x@W1^T+b1))            (B,4096)
//        h2 = tanh(LN(h1@W2^T+b2))           (B,2048)
//        amp = h2@W3^T+b3                    (B,1024)
//  ph:   p  = silu(LN(x@pW1^T+pb1))          (B,2048)
//        phase = tanh(p@pW2^T+pb2)           (B,1024)
//  qs = (sin(amp*f0+p0)+cos(phase*f1+p1)+tanh(p2))/3
//  v = qs @ attn_in_w[2048:3072]^T + attn_in_b[2048:]   (only V slice used!)
//  out = v @ attn_out_w^T + attn_out_b
// ---------------------------------------------------------------------------

#define PACK_F32X2(out, lo, hi) \
    asm("mov.b64 %0, {%1, %2};" : "=l"(out) : "f"(lo), "f"(hi))
#define UNPACK_F32X2(lo, hi, in) \
    asm("mov.b64 {%0, %1}, %2;" : "=f"(lo), "=f"(hi) : "l"(in))
#define FMA_F32X2(d, a, b, c) \
    asm("fma.rn.f32x2 %0, %1, %2, %3;" : "=l"(d) : "l"(a), "l"(b), "l"(c))

// Scratch (static device globals; no allocation in kernel_launch)
__device__ float g_h1[(size_t)16384 * 4096];   // 256 MB
__device__ float g_p [(size_t)16384 * 2048];   // 128 MB
__device__ float g_t2[(size_t)16384 * 2048];   // 128 MB
__device__ float g_amp[(size_t)16384 * 1024];  // 64 MB
__device__ float g_ph [(size_t)16384 * 1024];  // 64 MB
__device__ float g_qs [(size_t)16384 * 1024];  // 64 MB
__device__ float g_v  [(size_t)16384 * 1024];  // 64 MB

// ---------------------------------------------------------------------------
// Block-wide reduction of (sum, sumsq)
// ---------------------------------------------------------------------------
__device__ __forceinline__ float2 block_reduce2(float2 v, float2* sb) {
    const int lane = threadIdx.x & 31;
    const int wid  = threadIdx.x >> 5;
#pragma unroll
    for (int o = 16; o > 0; o >>= 1) {
        v.x += __shfl_xor_sync(0xffffffffu, v.x, o);
        v.y += __shfl_xor_sync(0xffffffffu, v.y, o);
    }
    if (lane == 0) sb[wid] = v;
    __syncthreads();
    if (wid == 0) {
        float2 t = (lane < 8) ? sb[lane] : make_float2(0.f, 0.f);
#pragma unroll
        for (int o = 4; o > 0; o >>= 1) {
            t.x += __shfl_xor_sync(0xffffffffu, t.x, o);
            t.y += __shfl_xor_sync(0xffffffffu, t.y, o);
        }
        if (lane == 0) sb[0] = t;
    }
    __syncthreads();
    float2 r = sb[0];
    __syncthreads();   // protect sb reuse by next call
    return r;
}

// ---------------------------------------------------------------------------
// Layer-1 for both branches, fused per row (F=2 so the matmul is 2 FMAs/elem)
// ---------------------------------------------------------------------------
__global__ __launch_bounds__(256)
void layer1_kernel(const float* __restrict__ x,
                   const float* __restrict__ aW1, const float* __restrict__ ab1,
                   const float* __restrict__ ag1, const float* __restrict__ abe1,
                   const float* __restrict__ pW1, const float* __restrict__ pb1,
                   const float* __restrict__ pg1, const float* __restrict__ pbe1,
                   float* __restrict__ h1, float* __restrict__ p)
{
    __shared__ float2 sb[8];
    const int b = blockIdx.x;
    const int tid = threadIdx.x;
    const float x0 = x[2 * b];
    const float x1 = x[2 * b + 1];

    // ---- amp branch: 4096 pre-activations, LN, GELU(exact) ----
    {
        float va[16];
        float2 ss = make_float2(0.f, 0.f);
#pragma unroll
        for (int t = 0; t < 16; t++) {
            const int i = tid + t * 256;
            const float2 w = *(const float2*)&aW1[2 * i];
            const float v = fmaf(w.y, x1, fmaf(w.x, x0, ab1[i]));
            va[t] = v;
            ss.x += v; ss.y += v * v;
        }
        const float2 r = block_reduce2(ss, sb);
        const float m = r.x * (1.f / 4096.f);
        const float rstd = rsqrtf(r.y * (1.f / 4096.f) - m * m + 1e-5f);
#pragma unroll
        for (int t = 0; t < 16; t++) {
            const int i = tid + t * 256;
            const float hh = (va[t] - m) * rstd * ag1[i] + abe1[i];
            h1[(size_t)b * 4096 + i] =
                0.5f * hh * (1.f + erff(hh * 0.70710678118654752f));
        }
    }

    // ---- phase branch: 2048 pre-activations, LN, SiLU ----
    {
        float vp[8];
        float2 ss = make_float2(0.f, 0.f);
#pragma unroll
        for (int t = 0; t < 8; t++) {
            const int i = tid + t * 256;
            const float2 w = *(const float2*)&pW1[2 * i];
            const float v = fmaf(w.y, x1, fmaf(w.x, x0, pb1[i]));
            vp[t] = v;
            ss.x += v; ss.y += v * v;
        }
        const float2 r = block_reduce2(ss, sb);
        const float m = r.x * (1.f / 2048.f);
        const float rstd = rsqrtf(r.y * (1.f / 2048.f) - m * m + 1e-5f);
#pragma unroll
        for (int t = 0; t < 8; t++) {
            const int i = tid + t * 256;
            const float hh = (vp[t] - m) * rstd * pg1[i] + pbe1[i];
            p[(size_t)b * 2048 + i] = hh / (1.f + expf(-hh));
        }
    }
}

// ---------------------------------------------------------------------------
// Row-wise LN + tanh over N=2048 (for amp layer-2)
// ---------------------------------------------------------------------------
__global__ __launch_bounds__(256)
void ln_tanh_kernel(const float* __restrict__ in,
                    const float* __restrict__ g, const float* __restrict__ be,
                    float* __restrict__ out)
{
    __shared__ float2 sb[8];
    const int b = blockIdx.x;
    const int tid = threadIdx.x;
    const float* row = in + (size_t)b * 2048;
    float va[8];
    float2 ss = make_float2(0.f, 0.f);
#pragma unroll
    for (int t = 0; t < 8; t++) {
        const int i = tid + t * 256;
        const float v = row[i];
        va[t] = v;
        ss.x += v; ss.y += v * v;
    }
    const float2 r = block_reduce2(ss, sb);
    const float m = r.x * (1.f / 2048.f);
    const float rstd = rsqrtf(r.y * (1.f / 2048.f) - m * m + 1e-5f);
#pragma unroll
    for (int t = 0; t < 8; t++) {
        const int i = tid + t * 256;
        out[(size_t)b * 2048 + i] = tanhf((va[t] - m) * rstd * g[i] + be[i]);
    }
}

// ---------------------------------------------------------------------------
// SGEMM (NT): C[m,n] = sum_k A[m,k] * W[n,k] + bias[n]   (EPI=1 -> tanh)
// A: (M,K) row-major, W: (N,K) row-major. M%128==0, N%128==0, K%16==0.
// 128x128 blocktile, BK=16, 256 threads, 8x8 microtile.
// Accumulators packed as f32x2 pairs along n -> FFMA2 (2x fp32 rate on sm_103a)
// ---------------------------------------------------------------------------
template<int EPI>
__global__ __launch_bounds__(256, 2)
void sgemm_nt(const float* __restrict__ A, const float* __restrict__ W,
              const float* __restrict__ bias, float* __restrict__ C,
              int M, int N, int K)
{
    __shared__ float As[16][128];
    __shared__ float Ws[16][128];

    const int tid = threadIdx.x;
    const int bm = blockIdx.y * 128;
    const int bn = blockIdx.x * 128;
    const int tx = tid & 15;   // n-dir (cols n0 = tx*8)
    const int ty = tid >> 4;   // m-dir (rows m0 = ty*8)

    const int lrow = tid >> 2;        // 0..63
    const int lc4  = (tid & 3) * 4;   // 0,4,8,12

    const float* Ag  = A + (size_t)(bm + lrow) * K + lc4;
    const float* Ag2 = Ag + (size_t)64 * K;
    const float* Wg  = W + (size_t)(bn + lrow) * K + lc4;
    const float* Wg2 = Wg + (size_t)64 * K;

    unsigned long long acc[8][4];
#pragma unroll
    for (int i = 0; i < 8; i++)
#pragma unroll
        for (int j = 0; j < 4; j++) acc[i][j] = 0ull;

    for (int k0 = 0; k0 < K; k0 += 16) {
        const float4 a0 = *(const float4*)(Ag + k0);
        const float4 a1 = *(const float4*)(Ag2 + k0);
        const float4 w0 = *(const float4*)(Wg + k0);
        const float4 w1 = *(const float4*)(Wg2 + k0);
        As[lc4 + 0][lrow]      = a0.x; As[lc4 + 1][lrow]      = a0.y;
        As[lc4 + 2][lrow]      = a0.z; As[lc4 + 3][lrow]      = a0.w;
        As[lc4 + 0][lrow + 64] = a1.x; As[lc4 + 1][lrow + 64] = a1.y;
        As[lc4 + 2][lrow + 64] = a1.z; As[lc4 + 3][lrow + 64] = a1.w;
        Ws[lc4 + 0][lrow]      = w0.x; Ws[lc4 + 1][lrow]      = w0.y;
        Ws[lc4 + 2][lrow]      = w0.z; Ws[lc4 + 3][lrow]      = w0.w;
        Ws[lc4 + 0][lrow + 64] = w1.x; Ws[lc4 + 1][lrow + 64] = w1.y;
        Ws[lc4 + 2][lrow + 64] = w1.z; Ws[lc4 + 3][lrow + 64] = w1.w;
        __syncthreads();

#pragma unroll
        for (int kk = 0; kk < 16; kk++) {
            const float4 alo = *(const float4*)&As[kk][ty * 8];
            const float4 ahi = *(const float4*)&As[kk][ty * 8 + 4];
            unsigned long long wp[4];
            wp[0] = *(const unsigned long long*)&Ws[kk][tx * 8 + 0];
            wp[1] = *(const unsigned long long*)&Ws[kk][tx * 8 + 2];
            wp[2] = *(const unsigned long long*)&Ws[kk][tx * 8 + 4];
            wp[3] = *(const unsigned long long*)&Ws[kk][tx * 8 + 6];
            const float av[8] = {alo.x, alo.y, alo.z, alo.w,
                                 ahi.x, ahi.y, ahi.z, ahi.w};
#pragma unroll
            for (int i = 0; i < 8; i++) {
                unsigned long long ap;
                PACK_F32X2(ap, av[i], av[i]);
#pragma unroll
                for (int j = 0; j < 4; j++)
                    FMA_F32X2(acc[i][j], ap, wp[j], acc[i][j]);
            }
        }
        __syncthreads();
    }

    // Epilogue: + bias, optional tanh; float2 stores
#pragma unroll
    for (int i = 0; i < 8; i++) {
        const int m = bm + ty * 8 + i;
        float* Cr = C + (size_t)m * N + bn + tx * 8;
        const float* br = bias + bn + tx * 8;
#pragma unroll
        for (int j = 0; j < 4; j++) {
            float lo, hi;
            UNPACK_F32X2(lo, hi, acc[i][j]);
            lo += br[2 * j];
            hi += br[2 * j + 1];
            if (EPI == 1) { lo = tanhf(lo); hi = tanhf(hi); }
            *(float2*)&Cr[2 * j] = make_float2(lo, hi);
        }
    }
}

// ---------------------------------------------------------------------------
// qs = (sin(amp*f0+p0) + cos(phase*f1+p1) + tanh(p2)) / 3   with rot[d=-1]
// ---------------------------------------------------------------------------
__global__ __launch_bounds__(256)
void qs_kernel(const float* __restrict__ amp, const float* __restrict__ ph,
               const float* __restrict__ rf, const float* __restrict__ rp,
               float* __restrict__ qs)
{
    const int idx = blockIdx.x * 256 + threadIdx.x;  // < 16384*1024
    const int q = idx & 1023;
    const float* f = rf + 4 * 1024 * 3 + 3 * q;   // rot_freq[-1, q, :]
    const float* pp = rp + 4 * 1024 * 3 + 3 * q;  // rot_phase[-1, q, :]
    const float rx = sinf(fmaf(amp[idx], f[0], pp[0]));
    const float ry = cosf(fmaf(ph[idx], f[1], pp[1]));
    const float rz = tanhf(pp[2]);
    qs[idx] = (rx + ry + rz) * (1.f / 3.f);
}

// ---------------------------------------------------------------------------
extern "C" void kernel_launch(void* const* d_in, const int* in_sizes, int n_in,
                              void* d_out, int out_size)
{
    const float* x     = (const float*)d_in[0];
    const float* aW1   = (const float*)d_in[1];
    const float* ab1   = (const float*)d_in[2];
    const float* ag1   = (const float*)d_in[3];
    const float* abe1  = (const float*)d_in[4];
    const float* aW2   = (const float*)d_in[5];
    const float* ab2   = (const float*)d_in[6];
    const float* ag2   = (const float*)d_in[7];
    const float* abe2  = (const float*)d_in[8];
    const float* aW3   = (const float*)d_in[9];
    const float* ab3   = (const float*)d_in[10];
    const float* pW1   = (const float*)d_in[11];
    const float* pb1   = (const float*)d_in[12];
    const float* pg1   = (const float*)d_in[13];
    const float* pbe1  = (const float*)d_in[14];
    const float* pW2   = (const float*)d_in[15];
    const float* pb2   = (const float*)d_in[16];
    const float* rf    = (const float*)d_in[17];
    const float* rp    = (const float*)d_in[18];
    const float* winV  = (const float*)d_in[19] + (size_t)2048 * 1024; // V rows only
    const float* binV  = (const float*)d_in[20] + 2048;
    const float* wout  = (const float*)d_in[21];
    const float* bout  = (const float*)d_in[22];
    float* out = (float*)d_out;

    float *h1, *p, *t2, *amp, *ph, *qs, *v;
    cudaGetSymbolAddress((void**)&h1,  g_h1);
    cudaGetSymbolAddress((void**)&p,   g_p);
    cudaGetSymbolAddress((void**)&t2,  g_t2);
    cudaGetSymbolAddress((void**)&amp, g_amp);
    cudaGetSymbolAddress((void**)&ph,  g_ph);
    cudaGetSymbolAddress((void**)&qs,  g_qs);
    cudaGetSymbolAddress((void**)&v,   g_v);

    const int M = 16384;

    // Stage 1: both layer-1s (fused matvec + LN + act)
    layer1_kernel<<<M, 256>>>(x, aW1, ab1, ag1, abe1, pW1, pb1, pg1, pbe1, h1, p);

    // Stage 2: amp layer-2 GEMM (16384x2048, K=4096), then LN+tanh
    sgemm_nt<0><<<dim3(2048 / 128, M / 128), 256>>>(h1, aW2, ab2, t2, M, 2048, 4096);
    ln_tanh_kernel<<<M, 256>>>(t2, ag2, abe2, t2);

    // Stage 3: amp = h2 @ W3^T + b3   (16384x1024, K=2048)
    sgemm_nt<0><<<dim3(1024 / 128, M / 128), 256>>>(t2, aW3, ab3, amp, M, 1024, 2048);

    // Stage 4: phase = tanh(p @ pW2^T + pb2)  (fused tanh epilogue)
    sgemm_nt<1><<<dim3(1024 / 128, M / 128), 256>>>(p, pW2, pb2, ph, M, 1024, 2048);

    // Stage 5: qs mixing
    qs_kernel<<<(M * 1024) / 256, 256>>>(amp, ph, rf, rp, qs);

    // Stage 6: v = qs @ Wv^T + bv   (only the V slice of attn_in)
    sgemm_nt<0><<<dim3(1024 / 128, M / 128), 256>>>(qs, winV, binV, v, M, 1024, 1024);

    // Stage 7: out = v @ attn_out_w^T + attn_out_b
    sgemm_nt<0><<<dim3(1024 / 128, M / 128), 256>>>(v, wout, bout, out, M, 1024, 1024);
}

// round 5
// speedup vs baseline: 3.2680x; 3.2680x over previous
#include <cuda_runtime.h>
#include <cuda_bf16.h>
#include <cstdint>

// ===========================================================================
// B=16384, Q=1024, F=2, D=5. Heavy GEMMs on tensor cores via mma.sync bf16
// (arch-portable PTX; tcgen05 is unavailable at this ptxas target) with
// hi/lo bf16 split: A*B ~= Ah*Bh + Ah*Bl + Al*Bh  (fp32 accumulate).
// ===========================================================================

#define DEVI __device__ __forceinline__

DEVI uint32_t smem_u32(const void* p) {
    uint32_t r;
    asm("{ .reg .u64 t; cvta.to.shared.u64 t, %1; cvt.u32.u64 %0, t; }"
        : "=r"(r) : "l"(p));
    return r;
}
DEVI uint32_t swz(uint32_t x) { return x ^ ((x >> 3) & 0x70); }

DEVI void cp16(uint32_t dst, const void* src) {
    asm volatile("cp.async.cg.shared.global [%0], [%1], 16;"
                 :: "r"(dst), "l"(src));
}
#define CP_COMMIT() asm volatile("cp.async.commit_group;" ::: "memory")
#define CP_WAIT(n)  asm volatile("cp.async.wait_group %0;" :: "n"(n) : "memory")

DEVI void ldsm4(uint32_t* r, uint32_t a) {
    asm volatile("ldmatrix.sync.aligned.m8n8.x4.shared.b16 {%0,%1,%2,%3}, [%4];"
                 : "=r"(r[0]), "=r"(r[1]), "=r"(r[2]), "=r"(r[3]) : "r"(a));
}
DEVI void mma_bf16(float* d, const uint32_t* a, const uint32_t* b) {
    asm volatile("mma.sync.aligned.m16n8k16.row.col.f32.bf16.bf16.f32 "
                 "{%0,%1,%2,%3},{%4,%5,%6,%7},{%8,%9},{%0,%1,%2,%3};"
                 : "+f"(d[0]), "+f"(d[1]), "+f"(d[2]), "+f"(d[3])
                 : "r"(a[0]), "r"(a[1]), "r"(a[2]), "r"(a[3]),
                   "r"(b[0]), "r"(b[1]));
}

DEVI void split_bf(float v, __nv_bfloat16& h, __nv_bfloat16& l) {
    h = __float2bfloat16(v);
    l = __float2bfloat16(v - __bfloat162float(h));
}
DEVI uint32_t pack2(__nv_bfloat16 a, __nv_bfloat16 b) {
    return (uint32_t)__bfloat16_as_ushort(a) | ((uint32_t)__bfloat16_as_ushort(b) << 16);
}

// ---------------------------------------------------------------------------
// Scratch
// ---------------------------------------------------------------------------
__device__ __nv_bfloat16 g_h1h[(size_t)16384 * 4096], g_h1l[(size_t)16384 * 4096];
__device__ __nv_bfloat16 g_ph_h[(size_t)16384 * 2048], g_ph_l[(size_t)16384 * 2048];
__device__ float         g_t2f[(size_t)16384 * 2048];
__device__ __nv_bfloat16 g_t2h[(size_t)16384 * 2048], g_t2l[(size_t)16384 * 2048];
__device__ float         g_ampf[(size_t)16384 * 1024], g_phf[(size_t)16384 * 1024];
__device__ __nv_bfloat16 g_qsh[(size_t)16384 * 1024], g_qsl[(size_t)16384 * 1024];
__device__ __nv_bfloat16 g_vh[(size_t)16384 * 1024],  g_vl[(size_t)16384 * 1024];
__device__ __nv_bfloat16 g_w2h[(size_t)2048 * 4096], g_w2l[(size_t)2048 * 4096];
__device__ __nv_bfloat16 g_w3h[(size_t)1024 * 2048], g_w3l[(size_t)1024 * 2048];
__device__ __nv_bfloat16 g_pw2h[(size_t)1024 * 2048], g_pw2l[(size_t)1024 * 2048];
__device__ __nv_bfloat16 g_wvh[(size_t)1024 * 1024], g_wvl[(size_t)1024 * 1024];
__device__ __nv_bfloat16 g_woh[(size_t)1024 * 1024], g_wol[(size_t)1024 * 1024];

// ---------------------------------------------------------------------------
// GEMM: C[m,n] = sum_k A[m,k]*W[n,k] + bias[n]
// A (M,K) / W (N,K) bf16 hi/lo planes. 128x128x64 tiles, 3-stage cp.async,
// 8 warps x (64x32) warp tiles of mma.sync m16n8k16 bf16.
// EPI: 0 = fp32 store, 1 = tanh+fp32, 2 = bf16 hi/lo split store
// ---------------------------------------------------------------------------
template<int EPI>
__global__ __launch_bounds__(256, 1)
void gemm_bf3(const __nv_bfloat16* __restrict__ Ahi, const __nv_bfloat16* __restrict__ Alo,
              const __nv_bfloat16* __restrict__ Bhi, const __nv_bfloat16* __restrict__ Blo,
              const float* __restrict__ bias,
              float* __restrict__ Cf,
              __nv_bfloat16* __restrict__ Chi, __nv_bfloat16* __restrict__ Clo,
              int N, int K)
{
    extern __shared__ char smem[];
    const uint32_t sb = smem_u32(smem);
    const uint32_t TILES = (sb + 1023u) & ~1023u;   // 1024-aligned for SW128

    const int tid    = threadIdx.x;
    const int wid    = tid >> 5;
    const int lane   = tid & 31;
    const int bm     = blockIdx.y * 128;
    const int bn     = blockIdx.x * 128;
    const int warp_m = wid & 1;        // 0..1 -> 64-row slab
    const int warp_n = wid >> 1;       // 0..3 -> 32-col slab

    const int nC = K >> 6;             // 64-wide K chunks

    auto load_chunk = [&](int ci, int s) {
        const int k0 = ci << 6;
        const uint32_t stg = TILES + s * 65536;
#pragma unroll
        for (int t = 0; t < 4; t++) {
            const int g = tid + t * 256;
            const int row = g >> 3;
            const int col8 = (g & 7) * 8;
            const uint32_t so = swz((uint32_t)(row * 128 + col8 * 2));
            const size_t ia = (size_t)(bm + row) * K + k0 + col8;
            const size_t ib = (size_t)(bn + row) * K + k0 + col8;
            cp16(stg + so,         Ahi + ia);
            cp16(stg + 16384 + so, Alo + ia);
            cp16(stg + 32768 + so, Bhi + ib);
            cp16(stg + 49152 + so, Blo + ib);
        }
        CP_COMMIT();
    };

    // Per-lane ldmatrix address components (group bits -> quadrant mapping)
    const uint32_t mA = warp_m * 64 + ((lane >> 3) & 1) * 8 + (lane & 7);
    const uint32_t kA = (lane >> 4) * 8;
    const uint32_t nB = warp_n * 32 + (lane >> 4) * 8 + (lane & 7);
    const uint32_t kB = ((lane >> 3) & 1) * 8;

    float acc[4][4][4];
#pragma unroll
    for (int i = 0; i < 4; i++)
#pragma unroll
        for (int j = 0; j < 4; j++)
#pragma unroll
            for (int e = 0; e < 4; e++) acc[i][j][e] = 0.f;

    load_chunk(0, 0);
    load_chunk(1, 1);

    for (int i = 0; i < nC; i++) {
        const int s = i - (i / 3) * 3;
        if (i + 1 < nC) { CP_WAIT(1); } else { CP_WAIT(0); }
        __syncthreads();
        if (i + 2 < nC) load_chunk(i + 2, (i + 2) - ((i + 2) / 3) * 3);

        const uint32_t stg = TILES + s * 65536;
        const uint32_t Ah_b = stg, Al_b = stg + 16384;
        const uint32_t Bh_b = stg + 32768, Bl_b = stg + 49152;

#pragma unroll
        for (int ks = 0; ks < 4; ks++) {
            const uint32_t offB0 = swz(nB * 128 + (ks * 16 + kB) * 2);
            const uint32_t offB1 = swz((nB + 16) * 128 + (ks * 16 + kB) * 2);
            uint32_t bh[2][4], bl[2][4];
            ldsm4(bh[0], Bh_b + offB0);
            ldsm4(bh[1], Bh_b + offB1);
            ldsm4(bl[0], Bl_b + offB0);
            ldsm4(bl[1], Bl_b + offB1);
#pragma unroll
            for (int mi = 0; mi < 4; mi++) {
                const uint32_t offA = swz((mA + mi * 16) * 128 + (ks * 16 + kA) * 2);
                uint32_t ah[4], al[4];
                ldsm4(ah, Ah_b + offA);
                ldsm4(al, Al_b + offA);
#pragma unroll
                for (int ni = 0; ni < 4; ni++) {
                    const uint32_t* bhp = &bh[ni >> 1][(ni & 1) * 2];
                    const uint32_t* blp = &bl[ni >> 1][(ni & 1) * 2];
                    mma_bf16(acc[mi][ni], ah, bhp);
                    mma_bf16(acc[mi][ni], ah, blp);
                    mma_bf16(acc[mi][ni], al, bhp);
                }
            }
        }
    }

    // ---- Epilogue ----
    const int r0l   = lane >> 2;           // row within 8-row group
    const int cpair = (lane & 3) * 2;      // col pair within 8-col frag
    const int mbase = bm + warp_m * 64;
    const int nbase = bn + warp_n * 32;

#pragma unroll
    for (int mi = 0; mi < 4; mi++) {
        const int row0 = mbase + mi * 16 + r0l;
        const int row1 = row0 + 8;
#pragma unroll
        for (int ni = 0; ni < 4; ni++) {
            const int col = nbase + ni * 8 + cpair;
            const float2 bv = *(const float2*)&bias[col];
            float v0 = acc[mi][ni][0] + bv.x;
            float v1 = acc[mi][ni][1] + bv.y;
            float v2 = acc[mi][ni][2] + bv.x;
            float v3 = acc[mi][ni][3] + bv.y;
            if (EPI == 1) {
                v0 = tanhf(v0); v1 = tanhf(v1); v2 = tanhf(v2); v3 = tanhf(v3);
            }
            if (EPI == 2) {
                __nv_bfloat16 h0, l0, h1, l1;
                split_bf(v0, h0, l0); split_bf(v1, h1, l1);
                *(uint32_t*)&Chi[(size_t)row0 * N + col] = pack2(h0, h1);
                *(uint32_t*)&Clo[(size_t)row0 * N + col] = pack2(l0, l1);
                split_bf(v2, h0, l0); split_bf(v3, h1, l1);
                *(uint32_t*)&Chi[(size_t)row1 * N + col] = pack2(h0, h1);
                *(uint32_t*)&Clo[(size_t)row1 * N + col] = pack2(l0, l1);
            } else {
                *(float2*)&Cf[(size_t)row0 * N + col] = make_float2(v0, v1);
                *(float2*)&Cf[(size_t)row1 * N + col] = make_float2(v2, v3);
            }
        }
    }
}

// ---------------------------------------------------------------------------
// Elementwise / LN kernels
// ---------------------------------------------------------------------------
__device__ __forceinline__ float2 block_reduce2(float2 v, float2* sbuf) {
    const int lane = threadIdx.x & 31;
    const int wid  = threadIdx.x >> 5;
#pragma unroll
    for (int o = 16; o > 0; o >>= 1) {
        v.x += __shfl_xor_sync(0xffffffffu, v.x, o);
        v.y += __shfl_xor_sync(0xffffffffu, v.y, o);
    }
    if (lane == 0) sbuf[wid] = v;
    __syncthreads();
    if (wid == 0) {
        float2 t = (lane < 8) ? sbuf[lane] : make_float2(0.f, 0.f);
#pragma unroll
        for (int o = 4; o > 0; o >>= 1) {
            t.x += __shfl_xor_sync(0xffffffffu, t.x, o);
            t.y += __shfl_xor_sync(0xffffffffu, t.y, o);
        }
        if (lane == 0) sbuf[0] = t;
    }
    __syncthreads();
    float2 r = sbuf[0];
    __syncthreads();
    return r;
}

__global__ __launch_bounds__(256)
void layer1_kernel(const float* __restrict__ x,
                   const float* __restrict__ aW1, const float* __restrict__ ab1,
                   const float* __restrict__ ag1, const float* __restrict__ abe1,
                   const float* __restrict__ pW1, const float* __restrict__ pb1,
                   const float* __restrict__ pg1, const float* __restrict__ pbe1,
                   __nv_bfloat16* __restrict__ h1h, __nv_bfloat16* __restrict__ h1l,
                   __nv_bfloat16* __restrict__ pph, __nv_bfloat16* __restrict__ ppl)
{
    __shared__ float2 sbuf[8];
    const int b = blockIdx.x;
    const int tid = threadIdx.x;
    const float x0 = x[2 * b];
    const float x1 = x[2 * b + 1];

    {
        float va[16];
        float2 ss = make_float2(0.f, 0.f);
#pragma unroll
        for (int t = 0; t < 16; t++) {
            const int i = tid + t * 256;
            const float2 w = *(const float2*)&aW1[2 * i];
            const float v = fmaf(w.y, x1, fmaf(w.x, x0, ab1[i]));
            va[t] = v; ss.x += v; ss.y += v * v;
        }
        const float2 r = block_reduce2(ss, sbuf);
        const float m = r.x * (1.f / 4096.f);
        const float rstd = rsqrtf(r.y * (1.f / 4096.f) - m * m + 1e-5f);
#pragma unroll
        for (int t = 0; t < 16; t++) {
            const int i = tid + t * 256;
            const float hh = (va[t] - m) * rstd * ag1[i] + abe1[i];
            const float g = 0.5f * hh * (1.f + erff(hh * 0.70710678118654752f));
            __nv_bfloat16 h, l; split_bf(g, h, l);
            h1h[(size_t)b * 4096 + i] = h;
            h1l[(size_t)b * 4096 + i] = l;
        }
    }
    {
        float vp[8];
        float2 ss = make_float2(0.f, 0.f);
#pragma unroll
        for (int t = 0; t < 8; t++) {
            const int i = tid + t * 256;
            const float2 w = *(const float2*)&pW1[2 * i];
            const float v = fmaf(w.y, x1, fmaf(w.x, x0, pb1[i]));
            vp[t] = v; ss.x += v; ss.y += v * v;
        }
        const float2 r = block_reduce2(ss, sbuf);
        const float m = r.x * (1.f / 2048.f);
        const float rstd = rsqrtf(r.y * (1.f / 2048.f) - m * m + 1e-5f);
#pragma unroll
        for (int t = 0; t < 8; t++) {
            const int i = tid + t * 256;
            const float hh = (vp[t] - m) * rstd * pg1[i] + pbe1[i];
            const float s = hh / (1.f + expf(-hh));
            __nv_bfloat16 h, l; split_bf(s, h, l);
            pph[(size_t)b * 2048 + i] = h;
            ppl[(size_t)b * 2048 + i] = l;
        }
    }
}

__global__ __launch_bounds__(256)
void ln_tanh_kernel(const float* __restrict__ in,
                    const float* __restrict__ g, const float* __restrict__ be,
                    __nv_bfloat16* __restrict__ oh, __nv_bfloat16* __restrict__ ol)
{
    __shared__ float2 sbuf[8];
    const int b = blockIdx.x;
    const int tid = threadIdx.x;
    const float* row = in + (size_t)b * 2048;
    float va[8];
    float2 ss = make_float2(0.f, 0.f);
#pragma unroll
    for (int t = 0; t < 8; t++) {
        const int i = tid + t * 256;
        const float v = row[i];
        va[t] = v; ss.x += v; ss.y += v * v;
    }
    const float2 r = block_reduce2(ss, sbuf);
    const float m = r.x * (1.f / 2048.f);
    const float rstd = rsqrtf(r.y * (1.f / 2048.f) - m * m + 1e-5f);
#pragma unroll
    for (int t = 0; t < 8; t++) {
        const int i = tid + t * 256;
        const float v = tanhf((va[t] - m) * rstd * g[i] + be[i]);
        __nv_bfloat16 h, l; split_bf(v, h, l);
        oh[(size_t)b * 2048 + i] = h;
        ol[(size_t)b * 2048 + i] = l;
    }
}

__global__ __launch_bounds__(256)
void qs_kernel(const float* __restrict__ amp, const float* __restrict__ phv,
               const float* __restrict__ rf, const float* __restrict__ rp,
               __nv_bfloat16* __restrict__ qh, __nv_bfloat16* __restrict__ ql)
{
    const int idx = blockIdx.x * 256 + threadIdx.x;
    const int q = idx & 1023;
    const float* f  = rf + 4 * 1024 * 3 + 3 * q;
    const float* pp = rp + 4 * 1024 * 3 + 3 * q;
    const float rx = sinf(fmaf(amp[idx], f[0], pp[0]));
    const float ry = cosf(fmaf(phv[idx], f[1], pp[1]));
    const float rz = tanhf(pp[2]);
    const float v = (rx + ry + rz) * (1.f / 3.f);
    __nv_bfloat16 h, l; split_bf(v, h, l);
    qh[idx] = h; ql[idx] = l;
}

__global__ __launch_bounds__(256)
void conv_split_kernel(const float* __restrict__ s,
                       __nv_bfloat16* __restrict__ h, __nv_bfloat16* __restrict__ l,
                       int n)
{
    const int i = blockIdx.x * 256 + threadIdx.x;
    if (i < n) {
        __nv_bfloat16 hh, ll; split_bf(s[i], hh, ll);
        h[i] = hh; l[i] = ll;
    }
}

// ---------------------------------------------------------------------------
extern "C" void kernel_launch(void* const* d_in, const int* in_sizes, int n_in,
                              void* d_out, int out_size)
{
    const float* x    = (const float*)d_in[0];
    const float* aW1  = (const float*)d_in[1];
    const float* ab1  = (const float*)d_in[2];
    const float* ag1  = (const float*)d_in[3];
    const float* abe1 = (const float*)d_in[4];
    const float* aW2  = (const float*)d_in[5];
    const float* ab2  = (const float*)d_in[6];
    const float* ag2  = (const float*)d_in[7];
    const float* abe2 = (const float*)d_in[8];
    const float* aW3  = (const float*)d_in[9];
    const float* ab3  = (const float*)d_in[10];
    const float* pW1  = (const float*)d_in[11];
    const float* pb1  = (const float*)d_in[12];
    const float* pg1  = (const float*)d_in[13];
    const float* pbe1 = (const float*)d_in[14];
    const float* pW2  = (const float*)d_in[15];
    const float* pb2  = (const float*)d_in[16];
    const float* rf   = (const float*)d_in[17];
    const float* rp   = (const float*)d_in[18];
    const float* winV = (const float*)d_in[19] + (size_t)2048 * 1024;
    const float* binV = (const float*)d_in[20] + 2048;
    const float* wout = (const float*)d_in[21];
    const float* bout = (const float*)d_in[22];
    float* out = (float*)d_out;

    __nv_bfloat16 *h1h, *h1l, *pph, *ppl, *t2h, *t2l, *qsh, *qsl, *vh, *vl;
    __nv_bfloat16 *w2h, *w2l, *w3h, *w3l, *pw2h, *pw2l, *wvh, *wvl, *woh, *wol;
    float *t2f, *ampf, *phf;
    cudaGetSymbolAddress((void**)&h1h, g_h1h); cudaGetSymbolAddress((void**)&h1l, g_h1l);
    cudaGetSymbolAddress((void**)&pph, g_ph_h); cudaGetSymbolAddress((void**)&ppl, g_ph_l);
    cudaGetSymbolAddress((void**)&t2f, g_t2f);
    cudaGetSymbolAddress((void**)&t2h, g_t2h); cudaGetSymbolAddress((void**)&t2l, g_t2l);
    cudaGetSymbolAddress((void**)&ampf, g_ampf); cudaGetSymbolAddress((void**)&phf, g_phf);
    cudaGetSymbolAddress((void**)&qsh, g_qsh); cudaGetSymbolAddress((void**)&qsl, g_qsl);
    cudaGetSymbolAddress((void**)&vh, g_vh); cudaGetSymbolAddress((void**)&vl, g_vl);
    cudaGetSymbolAddress((void**)&w2h, g_w2h); cudaGetSymbolAddress((void**)&w2l, g_w2l);
    cudaGetSymbolAddress((void**)&w3h, g_w3h); cudaGetSymbolAddress((void**)&w3l, g_w3l);
    cudaGetSymbolAddress((void**)&pw2h, g_pw2h); cudaGetSymbolAddress((void**)&pw2l, g_pw2l);
    cudaGetSymbolAddress((void**)&wvh, g_wvh); cudaGetSymbolAddress((void**)&wvl, g_wvl);
    cudaGetSymbolAddress((void**)&woh, g_woh); cudaGetSymbolAddress((void**)&wol, g_wol);

    const int SMEMB = 1024 + 3 * 65536;   // 197,632 B
    cudaFuncSetAttribute(gemm_bf3<0>, cudaFuncAttributeMaxDynamicSharedMemorySize, SMEMB);
    cudaFuncSetAttribute(gemm_bf3<1>, cudaFuncAttributeMaxDynamicSharedMemorySize, SMEMB);
    cudaFuncSetAttribute(gemm_bf3<2>, cudaFuncAttributeMaxDynamicSharedMemorySize, SMEMB);

    const int M = 16384;

    // Weight hi/lo planes
    conv_split_kernel<<<(2048 * 4096) / 256, 256>>>(aW2, w2h, w2l, 2048 * 4096);
    conv_split_kernel<<<(1024 * 2048) / 256, 256>>>(aW3, w3h, w3l, 1024 * 2048);
    conv_split_kernel<<<(1024 * 2048) / 256, 256>>>(pW2, pw2h, pw2l, 1024 * 2048);
    conv_split_kernel<<<(1024 * 1024) / 256, 256>>>(winV, wvh, wvl, 1024 * 1024);
    conv_split_kernel<<<(1024 * 1024) / 256, 256>>>(wout, woh, wol, 1024 * 1024);

    // Layer 1 (matvec F=2 + LN + act) -> bf16 hi/lo planes
    layer1_kernel<<<M, 256>>>(x, aW1, ab1, ag1, abe1, pW1, pb1, pg1, pbe1,
                              h1h, h1l, pph, ppl);

    // amp L2: (16384x2048, K=4096) -> fp32; then LN+tanh -> hi/lo
    gemm_bf3<0><<<dim3(16, 128), 256, SMEMB>>>(h1h, h1l, w2h, w2l, ab2,
                                               t2f, nullptr, nullptr, 2048, 4096);
    ln_tanh_kernel<<<M, 256>>>(t2f, ag2, abe2, t2h, t2l);

    // amp = t2 @ W3^T + b3
    gemm_bf3<0><<<dim3(8, 128), 256, SMEMB>>>(t2h, t2l, w3h, w3l, ab3,
                                              ampf, nullptr, nullptr, 1024, 2048);

    // phase = tanh(p @ pW2^T + pb2)
    gemm_bf3<1><<<dim3(8, 128), 256, SMEMB>>>(pph, ppl, pw2h, pw2l, pb2,
                                              phf, nullptr, nullptr, 1024, 2048);

    // qs mixing -> bf16 hi/lo
    qs_kernel<<<(M * 1024) / 256, 256>>>(ampf, phf, rf, rp, qsh, qsl);

    // v = qs @ Wv^T + bv  (bf16 hi/lo epilogue)
    gemm_bf3<2><<<dim3(8, 128), 256, SMEMB>>>(qsh, qsl, wvh, wvl, binV,
                                              nullptr, vh, vl, 1024, 1024);

    // out = v @ Wout^T + bout
    gemm_bf3<0><<<dim3(8, 128), 256, SMEMB>>>(vh, vl, woh, wol, bout,
                                              out, nullptr, nullptr, 1024, 1024);
}